// round 12
// baseline (speedup 1.0000x reference)
#include <cuda_runtime.h>

// All-pairs N-body gravity — SINGLE graph node. Evidence: the math kernel is
// pinned at 36.0us (issue+fma-pipe floor), but every bench carries a fixed
// ~3.3us second-node cost (zero kernel == memset node, identical gap).
// Restructure to kill that node: each CTA owns 16 i-bodies x ALL 8192 j
// (16 j-slices of 512, one per half-warp group), packed f32x2 math with two
// independent chains per thread, per-warp shared staging (+syncwarp), then a
// cross-slice shared reduction and ONE plain STG per output element.
// No atomics -> no zero pass -> one node.

#define BLOCK   256
#define ITILE   16            // i-bodies per CTA
#define JSLICE  512           // j per slice (8192/16 slices)
#define CHUNK   64            // j staged per slice per iteration
#define CW      (CHUNK / 2)   // packed words per chunk = 32
#define NCHUNK  (JSLICE / CHUNK)
#define EPS2    0.0001f       // SOFTENING^2

typedef unsigned long long u64;

__device__ __forceinline__ u64 pack2(float lo, float hi) {
    u64 r;
    asm("mov.b64 %0, {%1, %2};" : "=l"(r)
        : "r"(__float_as_uint(lo)), "r"(__float_as_uint(hi)));
    return r;
}
__device__ __forceinline__ void unpack2(u64 v, float& lo, float& hi) {
    unsigned a, b;
    asm("mov.b64 {%0, %1}, %2;" : "=r"(a), "=r"(b) : "l"(v));
    lo = __uint_as_float(a);
    hi = __uint_as_float(b);
}
__device__ __forceinline__ u64 f2add(u64 a, u64 b) {
    u64 r; asm("add.rn.f32x2 %0, %1, %2;" : "=l"(r) : "l"(a), "l"(b)); return r;
}
__device__ __forceinline__ u64 f2mul(u64 a, u64 b) {
    u64 r; asm("mul.rn.f32x2 %0, %1, %2;" : "=l"(r) : "l"(a), "l"(b)); return r;
}
__device__ __forceinline__ u64 f2fma(u64 a, u64 b, u64 c) {
    u64 r; asm("fma.rn.f32x2 %0, %1, %2, %3;"
               : "=l"(r) : "l"(a), "l"(b), "l"(c)); return r;
}
__device__ __forceinline__ float rsq_mufu(float x) {
    float r; asm("rsqrt.approx.f32 %0, %1;" : "=f"(r) : "f"(x)); return r;
}

__global__ __launch_bounds__(BLOCK)
void nbody_forces_kernel(const float* __restrict__ pos,
                         const float* __restrict__ mass,
                         float* __restrict__ out) {
    // Per-warp staging: 8 warps x 2 half-slices x 32 packed words.
    __shared__ u64 swx[8][2][CW], swy[8][2][CW], swz[8][2][CW], swm[8][2][CW];
    // Cross-slice reduction: [slice][dim][i_local], padded stride (17).
    __shared__ float red[16][3][ITILE + 1];

    const int tid  = threadIdx.x;
    const int warp = tid >> 5;
    const int lane = tid & 31;
    const int il   = lane & 15;       // i within tile
    const int h    = lane >> 4;       // half: which of the warp's 2 slices
    const int s    = 2 * warp + h;    // this lane's j-slice (0..15)
    const int i    = blockIdx.x * ITILE + il;

    const float xi = pos[3 * i + 0];
    const float yi = pos[3 * i + 1];
    const float zi = pos[3 * i + 2];
    const u64 nxi  = pack2(-xi, -xi);
    const u64 nyi  = pack2(-yi, -yi);
    const u64 nzi  = pack2(-zi, -zi);
    const u64 eps22 = pack2(EPS2, EPS2);

    u64 axA = 0ull, ayA = 0ull, azA = 0ull;   // chain A
    u64 axB = 0ull, ayB = 0ull, azB = 0ull;   // chain B (independent)

    for (int c = 0; c < NCHUNK; ++c) {
        __syncwarp();
        // Stage both of this warp's slice-chunks (64 j each) cooperatively.
#pragma unroll
        for (int hh = 0; hh < 2; ++hh) {
            const int base = (2 * warp + hh) * JSLICE + c * CHUNK;
#pragma unroll
            for (int t = lane; t < CHUNK; t += 32) {
                int j = base + t;
                ((float*)swx[warp][hh])[t] = pos[3 * j + 0];
                ((float*)swy[warp][hh])[t] = pos[3 * j + 1];
                ((float*)swz[warp][hh])[t] = pos[3 * j + 2];
                ((float*)swm)[(warp * 2 + hh) * CHUNK + t] = mass[j];
            }
        }
        __syncwarp();

        const u64* bx = swx[warp][h];
        const u64* by = swy[warp][h];
        const u64* bz = swz[warp][h];
        const u64* bm = swm[warp][h];

#pragma unroll 4
        for (int t = 0; t < CW / 2; ++t) {
            // chain A: word t
            {
                u64 dx = f2add(bx[t], nxi);
                u64 dy = f2add(by[t], nyi);
                u64 dz = f2add(bz[t], nzi);
                u64 r2 = f2fma(dx, dx, f2fma(dy, dy, f2fma(dz, dz, eps22)));
                float a, b;
                unpack2(r2, a, b);
                u64 inv = pack2(rsq_mufu(a), rsq_mufu(b));
                u64 sc  = f2mul(bm[t], f2mul(f2mul(inv, inv), inv));
                axA = f2fma(sc, dx, axA);
                ayA = f2fma(sc, dy, ayA);
                azA = f2fma(sc, dz, azA);
            }
            // chain B: word t + 16 (independent)
            {
                const int u = t + CW / 2;
                u64 dx = f2add(bx[u], nxi);
                u64 dy = f2add(by[u], nyi);
                u64 dz = f2add(bz[u], nzi);
                u64 r2 = f2fma(dx, dx, f2fma(dy, dy, f2fma(dz, dz, eps22)));
                float a, b;
                unpack2(r2, a, b);
                u64 inv = pack2(rsq_mufu(a), rsq_mufu(b));
                u64 sc  = f2mul(bm[u], f2mul(f2mul(inv, inv), inv));
                axB = f2fma(sc, dx, axB);
                ayB = f2fma(sc, dy, ayB);
                azB = f2fma(sc, dz, azB);
            }
        }
    }

    // Merge chains -> per-(slice, i) partial; reduce across slices in shared.
    float l, hf;
    unpack2(f2add(axA, axB), l, hf); red[s][0][il] = l + hf;
    unpack2(f2add(ayA, ayB), l, hf); red[s][1][il] = l + hf;
    unpack2(f2add(azA, azB), l, hf); red[s][2][il] = l + hf;
    __syncthreads();

    if (tid < ITILE * 3) {
        const int ii  = tid & 15;
        const int dim = tid >> 4;     // 0..2
        float v = 0.0f;
#pragma unroll
        for (int ss = 0; ss < 16; ++ss) v += red[ss][dim][ii];
        out[3 * (blockIdx.x * ITILE + ii) + dim] = v;   // single plain store
    }
}

extern "C" void kernel_launch(void* const* d_in, const int* in_sizes, int n_in,
                              void* d_out, int out_size) {
    const float* pos  = (const float*)d_in[0];   // [N,3] float32
    const float* mass = (const float*)d_in[1];   // [N]   float32
    float* out = (float*)d_out;                  // [N,3] float32

    const int n = in_sizes[0] / 3;               // 8192

    // One node, no atomics, no zeroing: every out element stored exactly once.
    nbody_forces_kernel<<<n / ITILE, BLOCK>>>(pos, mass, out);
}